// round 2
// baseline (speedup 1.0000x reference)
#include <cuda_runtime.h>
#include <math.h>
#include <stdint.h>

#define B 32
#define S 512
#define H 256
#define T 48
#define START_IDX 46
#define STOP_IDX 47
#define RESCALE_PERIOD 5

// Scratch (no allocations allowed): exp(emission) and emission-at-gold-tag
__device__ float g_expEm[B * S * T];    // 3 MB
__device__ float g_emAtTag[B * S];      // 64 KB

#define FMA2(acc, a, b) \
    asm("fma.rn.f32x2 %0, %1, %2, %0;" : "+l"(acc) : "l"(a), "l"(b))
#define PACK2(out, lo, hi) \
    asm("mov.b64 %0, {%1, %2};" : "=l"(out) : "f"(lo), "f"(hi))
#define UNPACK2(lo, hi, in) \
    asm("mov.b64 {%0, %1}, %2;" : "=f"(lo), "=f"(hi) : "l"(in))

// ---------------------------------------------------------------------------
// Kernel A: emission = feat @ W + bias; store exp(emission) and em[b,s,tags[b,s]]
// Grid: 128 blocks x 256 threads. Each block: 128 rows x 48 cols, K=256.
// ---------------------------------------------------------------------------
__global__ __launch_bounds__(256) void emis_kernel(
    const float* __restrict__ feat,   // [B*S, H]
    const float* __restrict__ Wm,     // [H, T]
    const float* __restrict__ bias,   // [T]
    const int*   __restrict__ tags)   // [B*S]
{
    const int P = 129;                       // smem pitch (conflict break)
    __shared__ float sh_W[64 * T];           // 12 KB
    __shared__ float sh_feat[64 * P];        // 33 KB  (transposed: [k][row])

    const int tid  = threadIdx.x;
    const int row0 = blockIdx.x * 128;
    const int rg   = tid >> 3;   // 0..31 -> rows rg*4..rg*4+3
    const int cg   = tid & 7;    // 0..7  -> cols cg*6..cg*6+5

    float acc[4][6];
#pragma unroll
    for (int r = 0; r < 4; r++)
#pragma unroll
        for (int c = 0; c < 6; c++) acc[r][c] = 0.0f;

    for (int kc = 0; kc < H; kc += 64) {
        for (int u = tid; u < 64 * T; u += 256) sh_W[u] = Wm[kc * T + u];

#pragma unroll
        for (int m = 0; m < 8; m++) {
            int u   = tid + m * 256;      // 0..2047
            int row = u >> 4;             // 0..127
            int k4  = u & 15;             // 0..15 (float4 index)
            float4 v = reinterpret_cast<const float4*>(feat)
                        [(size_t)(row0 + row) * (H / 4) + (kc >> 2) + k4];
            sh_feat[(k4 * 4 + 0) * P + row] = v.x;
            sh_feat[(k4 * 4 + 1) * P + row] = v.y;
            sh_feat[(k4 * 4 + 2) * P + row] = v.z;
            sh_feat[(k4 * 4 + 3) * P + row] = v.w;
        }
        __syncthreads();

#pragma unroll 16
        for (int k = 0; k < 64; k++) {
            float f0 = sh_feat[k * P + rg * 4 + 0];
            float f1 = sh_feat[k * P + rg * 4 + 1];
            float f2 = sh_feat[k * P + rg * 4 + 2];
            float f3 = sh_feat[k * P + rg * 4 + 3];
            float2 w01 = *reinterpret_cast<const float2*>(&sh_W[k * T + cg * 6 + 0]);
            float2 w23 = *reinterpret_cast<const float2*>(&sh_W[k * T + cg * 6 + 2]);
            float2 w45 = *reinterpret_cast<const float2*>(&sh_W[k * T + cg * 6 + 4]);
            float w[6] = {w01.x, w01.y, w23.x, w23.y, w45.x, w45.y};
            float f[4] = {f0, f1, f2, f3};
#pragma unroll
            for (int r = 0; r < 4; r++)
#pragma unroll
                for (int c = 0; c < 6; c++)
                    acc[r][c] = fmaf(f[r], w[c], acc[r][c]);
        }
        __syncthreads();
    }

#pragma unroll
    for (int rr = 0; rr < 4; rr++) {
        int row = row0 + rg * 4 + rr;
        int tag = __ldg(&tags[row]);
#pragma unroll
        for (int cc = 0; cc < 6; cc++) {
            int c = cg * 6 + cc;
            float em = acc[rr][cc] + __ldg(&bias[c]);
            g_expEm[(size_t)row * T + c] = expf(em);
            if (c == tag) g_emAtTag[row] = em;
        }
    }
}

// ---------------------------------------------------------------------------
// Kernel B: forward recursion in scaled-linear space + terminal LSE + gold.
// Grid: B blocks x 64 threads (thread j owns tag column j; j>=48 padded).
// a[j] = exp(alpha[j] - C); step: a'[j] = expEm[j] * dot(a, expT[:,j]).
//  - expEm prefetched 4 steps ahead (register ring, 4 LDG in flight)
//  - dot product via packed fma.rn.f32x2 (24 FFMA2 instead of 48 FFMA)
//  - rescale max-reduced at step s, applied at step s+1 (no extra barrier)
// ---------------------------------------------------------------------------
__global__ __launch_bounds__(64) void fwd_kernel(
    const float* __restrict__ trans,     // [T,T]
    const int*   __restrict__ lengths,   // [B]
    const int*   __restrict__ tags,      // [B,S]
    float*       __restrict__ out)       // [B]
{
    __shared__ float sh_trans[T * T];
    __shared__ __align__(16) float a_sh[2][64];
    __shared__ float red[2];

    const int tid  = threadIdx.x;
    const int b    = blockIdx.x;
    const int lane = tid & 31;
    const int wid  = tid >> 5;
    const int j    = tid;

    for (int u = tid; u < T * T; u += 64) sh_trans[u] = trans[u];
    __syncthreads();

    // per-thread transition column in registers, packed as f32x2 pairs
    unsigned long long eT2[T / 2];
    float eStop = 0.0f;
    if (j < T) {
#pragma unroll
        for (int i = 0; i < T / 2; i++) {
            float lo = expf(sh_trans[(2 * i + 0) * T + j]);
            float hi = expf(sh_trans[(2 * i + 1) * T + j]);
            PACK2(eT2[i], lo, hi);
        }
        eStop = expf(sh_trans[j * T + STOP_IDX]);
    } else {
#pragma unroll
        for (int i = 0; i < T / 2; i++) eT2[i] = 0ull;
    }

    a_sh[0][tid] = (tid == START_IDX) ? 1.0f : 0.0f;
    __syncthreads();

    const int len = lengths[b];
    const float* pe = g_expEm + (size_t)b * S * T + j;

    // base shared addresses of the two a-buffers
    const uint32_t abase0 = (uint32_t)__cvta_generic_to_shared(&a_sh[0][0]);
    const uint32_t abase1 = (uint32_t)__cvta_generic_to_shared(&a_sh[1][0]);

    // expEm prefetch ring, depth 4
    float Ebuf[4];
#pragma unroll
    for (int q = 0; q < 4; q++)
        Ebuf[q] = (j < T && q < len) ? pe[(size_t)q * T] : 0.0f;

    float C    = 0.0f;
    int   buf  = 0;
    int   cnt  = 0;
    bool  apply = false;
    float invM = 1.0f, logM = 0.0f;

    for (int s = 0; s < len; s++) {
        const uint32_t ab = buf ? abase1 : abase0;

        unsigned long long acc0 = 0ull, acc1 = 0ull, acc2 = 0ull, acc3 = 0ull;
#pragma unroll
        for (int q = 0; q < 6; q++) {
            unsigned long long x, y;
            asm("ld.shared.v2.u64 {%0, %1}, [%2];"
                : "=l"(x), "=l"(y) : "r"(ab + q * 16));
            if (q & 1) { FMA2(acc2, x, eT2[4 * q]); FMA2(acc3, y, eT2[4 * q + 2]); }
            else       { FMA2(acc0, x, eT2[4 * q]); FMA2(acc1, y, eT2[4 * q + 2]); }
            unsigned long long x2, y2;
            // second half of this 16B chunk's pairs (pairs 4q+1, 4q+3)
            // NOTE: pairs within x are (a[8q],a[8q+1]) and within y (a[8q+2],a[8q+3])
            // handled above; the layout below covers the remaining pairs.
            (void)x2; (void)y2;
        }
        // The loop above consumed pairs {8q..8q+3} per q via x,y each holding 2 floats:
        // x = (a[8q],a[8q+1]) pairs with eT2[4q]; y = (a[8q+2],a[8q+3]) with eT2[4q+1].
        // Fix indexing: redo with correct eT2 indices (see below) — compile-time unrolled.

        // ---- correct accumulation (overrides above: accs recomputed) ----
        acc0 = 0ull; acc1 = 0ull; acc2 = 0ull; acc3 = 0ull;
#pragma unroll
        for (int q = 0; q < 12; q++) {
            unsigned long long x, y;
            asm("ld.shared.v2.u64 {%0, %1}, [%2];"
                : "=l"(x), "=l"(y) : "r"(ab + q * 16));
            FMA2(acc0, x, eT2[2 * q + 0]);
            FMA2(acc1, y, eT2[2 * q + 1]);
            q++;  // manual 2x: next 16B chunk into acc2/acc3
            if (q < 12) {
                unsigned long long x2, y2;
                asm("ld.shared.v2.u64 {%0, %1}, [%2];"
                    : "=l"(x2), "=l"(y2) : "r"(ab + q * 16));
                FMA2(acc2, x2, eT2[2 * q + 0]);
                FMA2(acc3, y2, eT2[2 * q + 1]);
            }
        }

        float l0, h0, l1, h1, l2, h2, l3, h3;
        UNPACK2(l0, h0, acc0); UNPACK2(l1, h1, acc1);
        UNPACK2(l2, h2, acc2); UNPACK2(l3, h3, acc3);
        float dot = ((l0 + h0) + (l1 + h1)) + ((l2 + h2) + (l3 + h3));

        float val = Ebuf[s & 3] * dot;
        if (apply) { val *= invM; C += logM; }

        // prefetch expEm for step s+4
        {
            int sp = s + 4;
            float ld = 0.0f;
            if (j < T && sp < len) ld = pe[(size_t)sp * T];
            Ebuf[sp & 3] = ld;
        }

        const int nbuf = buf ^ 1;
        a_sh[nbuf][tid] = val;

        bool red_now = (++cnt == RESCALE_PERIOD);
        if (red_now) {
            cnt = 0;
            float m = val;
#pragma unroll
            for (int o = 16; o; o >>= 1)
                m = fmaxf(m, __shfl_xor_sync(0xffffffffu, m, o));
            if (lane == 0) red[wid] = m;
        }
        __syncthreads();
        if (red_now) {
            float M = fmaxf(red[0], red[1]);
            invM = 1.0f / M;
            logM = logf(M);
            apply = true;
        } else {
            apply = false;
        }
        buf = nbuf;
    }

    // terminal: logZ = C + log( sum_j a[j] * exp(trans[j][STOP]) )
    float tj = (j < T) ? a_sh[buf][j] * eStop : 0.0f;
#pragma unroll
    for (int o = 16; o; o >>= 1) tj += __shfl_xor_sync(0xffffffffu, tj, o);
    __syncthreads();   // ensure red[] from loop no longer needed before overwrite
    if (lane == 0) red[wid] = tj;
    __syncthreads();
    const float logZ = C + logf(red[0] + red[1]);
    __syncthreads();   // before reusing red[]

    // gold score
    const int* btags = tags + b * S;
    float g = 0.0f;
    for (int s = tid; s < len; s += 64) {
        int to   = btags[s];
        int from = (s == 0) ? START_IDX : btags[s - 1];
        g += sh_trans[from * T + to] + g_emAtTag[(size_t)b * S + s];
    }
#pragma unroll
    for (int o = 16; o; o >>= 1) g += __shfl_xor_sync(0xffffffffu, g, o);
    if (lane == 0) red[wid] = g;
    __syncthreads();

    if (tid == 0) {
        float gold = red[0] + red[1] + sh_trans[btags[len - 1] * T + STOP_IDX];
        out[b] = logZ - gold;
    }
}

// ---------------------------------------------------------------------------
extern "C" void kernel_launch(void* const* d_in, const int* in_sizes, int n_in,
                              void* d_out, int out_size)
{
    const float* feat    = (const float*)d_in[0];  // lstm_features [B,S,H]
    const float* Wm      = (const float*)d_in[1];  // emission_w [H,T]
    const float* bias    = (const float*)d_in[2];  // emission_b [T]
    const float* trans   = (const float*)d_in[3];  // transitions [T,T]
    const int*   lengths = (const int*)d_in[4];    // [B]
    const int*   tags    = (const int*)d_in[5];    // [B,S]
    float*       out     = (float*)d_out;          // [B]

    emis_kernel<<<(B * S) / 128, 256>>>(feat, Wm, bias, tags);
    fwd_kernel<<<B, 64>>>(trans, lengths, tags, out);
}

// round 4
// speedup vs baseline: 2.0280x; 2.0280x over previous
#include <cuda_runtime.h>
#include <math.h>
#include <stdint.h>

#define B 32
#define S 512
#define H 256
#define T 48
#define START_IDX 46
#define STOP_IDX 47

// Scratch (no allocations allowed): exp(emission) and emission-at-gold-tag
__device__ float g_expEm[B * S * T];    // 3 MB
__device__ float g_emAtTag[B * S];      // 64 KB

#define FMA2(acc, a, b) \
    asm("fma.rn.f32x2 %0, %1, %2, %0;" : "+l"(acc) : "l"(a), "l"(b))
#define ADD2(out, a, b) \
    asm("add.rn.f32x2 %0, %1, %2;" : "=l"(out) : "l"(a), "l"(b))
#define PACK2(out, lo, hi) \
    asm("mov.b64 %0, {%1, %2};" : "=l"(out) : "f"(lo), "f"(hi))
#define UNPACK2(lo, hi, in) \
    asm("mov.b64 {%0, %1}, %2;" : "=f"(lo), "=f"(hi) : "l"(in))

// ---------------------------------------------------------------------------
// Kernel A: emission = feat @ W + bias; store exp(emission) and em[b,s,tags[b,s]]
// Grid: 128 blocks x 256 threads. Each block: 128 rows x 48 cols, K=256.
// ---------------------------------------------------------------------------
__global__ __launch_bounds__(256) void emis_kernel(
    const float* __restrict__ feat,   // [B*S, H]
    const float* __restrict__ Wm,     // [H, T]
    const float* __restrict__ bias,   // [T]
    const int*   __restrict__ tags)   // [B*S]
{
    const int P = 129;                       // smem pitch (conflict break)
    __shared__ float sh_W[64 * T];           // 12 KB
    __shared__ float sh_feat[64 * P];        // 33 KB  (transposed: [k][row])

    const int tid  = threadIdx.x;
    const int row0 = blockIdx.x * 128;
    const int rg   = tid >> 3;   // 0..31 -> rows rg*4..rg*4+3
    const int cg   = tid & 7;    // 0..7  -> cols cg*6..cg*6+5

    float acc[4][6];
#pragma unroll
    for (int r = 0; r < 4; r++)
#pragma unroll
        for (int c = 0; c < 6; c++) acc[r][c] = 0.0f;

    for (int kc = 0; kc < H; kc += 64) {
        for (int u = tid; u < 64 * T; u += 256) sh_W[u] = Wm[kc * T + u];

#pragma unroll
        for (int m = 0; m < 8; m++) {
            int u   = tid + m * 256;      // 0..2047
            int row = u >> 4;             // 0..127
            int k4  = u & 15;             // 0..15 (float4 index)
            float4 v = reinterpret_cast<const float4*>(feat)
                        [(size_t)(row0 + row) * (H / 4) + (kc >> 2) + k4];
            sh_feat[(k4 * 4 + 0) * P + row] = v.x;
            sh_feat[(k4 * 4 + 1) * P + row] = v.y;
            sh_feat[(k4 * 4 + 2) * P + row] = v.z;
            sh_feat[(k4 * 4 + 3) * P + row] = v.w;
        }
        __syncthreads();

#pragma unroll 16
        for (int k = 0; k < 64; k++) {
            float f0 = sh_feat[k * P + rg * 4 + 0];
            float f1 = sh_feat[k * P + rg * 4 + 1];
            float f2 = sh_feat[k * P + rg * 4 + 2];
            float f3 = sh_feat[k * P + rg * 4 + 3];
            float2 w01 = *reinterpret_cast<const float2*>(&sh_W[k * T + cg * 6 + 0]);
            float2 w23 = *reinterpret_cast<const float2*>(&sh_W[k * T + cg * 6 + 2]);
            float2 w45 = *reinterpret_cast<const float2*>(&sh_W[k * T + cg * 6 + 4]);
            float w[6] = {w01.x, w01.y, w23.x, w23.y, w45.x, w45.y};
            float f[4] = {f0, f1, f2, f3};
#pragma unroll
            for (int r = 0; r < 4; r++)
#pragma unroll
                for (int c = 0; c < 6; c++)
                    acc[r][c] = fmaf(f[r], w[c], acc[r][c]);
        }
        __syncthreads();
    }

#pragma unroll
    for (int rr = 0; rr < 4; rr++) {
        int row = row0 + rg * 4 + rr;
        int tag = __ldg(&tags[row]);
#pragma unroll
        for (int cc = 0; cc < 6; cc++) {
            int c = cg * 6 + cc;
            float em = acc[rr][cc] + __ldg(&bias[c]);
            g_expEm[(size_t)row * T + c] = expf(em);
            if (c == tag) g_emAtTag[row] = em;
        }
    }
}

// ---------------------------------------------------------------------------
// Kernel B: forward recursion in scaled-linear space + terminal LSE + gold.
// Grid: B blocks x 64 threads (thread j owns tag column j; j>=48 padded).
// a[j] = exp(alpha[j] - K*ln2); step: a'[j] = expEm[j] * dot(a, expT[:,j]).
//  - a-vector read via C++ ulonglong2 loads (proper memory ordering vs barrier)
//  - dot via 24 packed fma.rn.f32x2 into 4 accumulators
//  - power-of-2 rescale every 4 steps: redux.sync max, exponent by bit ops,
//    applied on the following step; integer K accounting (exact)
// ---------------------------------------------------------------------------
__global__ __launch_bounds__(64) void fwd_kernel(
    const float* __restrict__ trans,     // [T,T]
    const int*   __restrict__ lengths,   // [B]
    const int*   __restrict__ tags,      // [B,S]
    float*       __restrict__ out)       // [B]
{
    __shared__ float sh_trans[T * T];
    __shared__ __align__(16) float a_sh[2][64];
    __shared__ float red[2];

    const int tid  = threadIdx.x;
    const int b    = blockIdx.x;
    const int lane = tid & 31;
    const int wid  = tid >> 5;
    const int j    = tid;

    for (int u = tid; u < T * T; u += 64) sh_trans[u] = trans[u];
    __syncthreads();

    // per-thread transition column in registers, packed as f32x2 pairs
    unsigned long long eT2[T / 2];
    float eStop = 0.0f;
    if (j < T) {
#pragma unroll
        for (int i = 0; i < T / 2; i++) {
            float lo = expf(sh_trans[(2 * i + 0) * T + j]);
            float hi = expf(sh_trans[(2 * i + 1) * T + j]);
            PACK2(eT2[i], lo, hi);
        }
        eStop = expf(sh_trans[j * T + STOP_IDX]);
    } else {
#pragma unroll
        for (int i = 0; i < T / 2; i++) eT2[i] = 0ull;
    }

    a_sh[0][tid] = (tid == START_IDX) ? 1.0f : 0.0f;
    __syncthreads();

    const int len = lengths[b];
    const float* pe = g_expEm + (size_t)b * S * T + j;

    // expEm prefetch ring, depth 4
    float Ebuf[4];
#pragma unroll
    for (int q = 0; q < 4; q++)
        Ebuf[q] = (j < T && q < len) ? pe[(size_t)q * T] : 0.0f;

    int   K     = 0;       // total shifted-out exponent (exact)
    int   klast = 0;       // k of the most recent measure (for tail fixup)
    int   buf   = 0;
    float invM  = 1.0f;    // pending 2^-k to apply on next step

    for (int s = 0; s < len; s++) {
        const ulonglong2* av =
            reinterpret_cast<const ulonglong2*>(buf ? a_sh[1] : a_sh[0]);

        unsigned long long acc0 = 0ull, acc1 = 0ull, acc2 = 0ull, acc3 = 0ull;
#pragma unroll
        for (int q = 0; q < 12; q += 2) {
            ulonglong2 u = av[q];        // a[4q   .. 4q+3]
            ulonglong2 v = av[q + 1];    // a[4q+4 .. 4q+7]
            FMA2(acc0, u.x, eT2[2 * q + 0]);
            FMA2(acc1, u.y, eT2[2 * q + 1]);
            FMA2(acc2, v.x, eT2[2 * q + 2]);
            FMA2(acc3, v.y, eT2[2 * q + 3]);
        }
        unsigned long long t01, t23, t03;
        ADD2(t01, acc0, acc1);
        ADD2(t23, acc2, acc3);
        ADD2(t03, t01, t23);
        float dl, dh;
        UNPACK2(dl, dh, t03);
        float dot = dl + dh;

        // apply pending rescale (invM = 2^-k; identity when none pending)
        float val = Ebuf[s & 3] * dot * invM;
        invM = 1.0f;

        // prefetch expEm for step s+4
        {
            int sp = s + 4;
            float ld = 0.0f;
            if (j < T && sp < len) ld = pe[(size_t)sp * T];
            Ebuf[sp & 3] = ld;
        }

        const int nbuf = buf ^ 1;
        a_sh[nbuf][tid] = val;

        const bool red_now = ((s & 3) == 3);
        if (red_now) {
            // warp max of nonneg floats via u32 redux (u32 order == float order)
            uint32_t vbits = __float_as_uint(val);
            uint32_t wmax;
            asm volatile("redux.sync.max.u32 %0, %1, 0xffffffff;"
                         : "=r"(wmax) : "r"(vbits));
            if (lane == 0) red[wid] = __uint_as_float(wmax);
        }
        __syncthreads();
        if (red_now) {
            float M = fmaxf(red[0], red[1]);
            int   k = (int)(__float_as_uint(M) >> 23) - 127;   // M in [2^k, 2^(k+1))
            invM  = __uint_as_float((uint32_t)(127 - k) << 23); // exact 2^-k
            K    += k;
            klast = k;
        }
        buf = nbuf;
    }
    // if the loop ended on a measure step, its rescale was never applied
    if ((len & 3) == 0) K -= klast;

    // terminal: logZ = K*ln2 + log( sum_j a[j] * exp(trans[j][STOP]) )
    float tj = (j < T) ? a_sh[buf][j] * eStop : 0.0f;
#pragma unroll
    for (int o = 16; o; o >>= 1) tj += __shfl_xor_sync(0xffffffffu, tj, o);
    __syncthreads();
    if (lane == 0) red[wid] = tj;
    __syncthreads();
    const float logZ = (float)K * 0.6931471805599453f + logf(red[0] + red[1]);
    __syncthreads();   // before reusing red[]

    // gold score
    const int* btags = tags + b * S;
    float g = 0.0f;
    for (int s = tid; s < len; s += 64) {
        int to   = btags[s];
        int from = (s == 0) ? START_IDX : btags[s - 1];
        g += sh_trans[from * T + to] + g_emAtTag[(size_t)b * S + s];
    }
#pragma unroll
    for (int o = 16; o; o >>= 1) g += __shfl_xor_sync(0xffffffffu, g, o);
    if (lane == 0) red[wid] = g;
    __syncthreads();

    if (tid == 0) {
        float gold = red[0] + red[1] + sh_trans[btags[len - 1] * T + STOP_IDX];
        out[b] = logZ - gold;
    }
}

// ---------------------------------------------------------------------------
extern "C" void kernel_launch(void* const* d_in, const int* in_sizes, int n_in,
                              void* d_out, int out_size)
{
    const float* feat    = (const float*)d_in[0];  // lstm_features [B,S,H]
    const float* Wm      = (const float*)d_in[1];  // emission_w [H,T]
    const float* bias    = (const float*)d_in[2];  // emission_b [T]
    const float* trans   = (const float*)d_in[3];  // transitions [T,T]
    const int*   lengths = (const int*)d_in[4];    // [B]
    const int*   tags    = (const int*)d_in[5];    // [B,S]
    float*       out     = (float*)d_out;          // [B]

    emis_kernel<<<(B * S) / 128, 256>>>(feat, Wm, bias, tags);
    fwd_kernel<<<B, 64>>>(trans, lengths, tags, out);
}

// round 8
// speedup vs baseline: 2.7695x; 1.3657x over previous
#include <cuda_runtime.h>
#include <math.h>
#include <stdint.h>

#define B 32
#define S 512
#define H 256
#define T 48
#define START_IDX 46
#define STOP_IDX 47

// Scratch (no allocations allowed): exp(emission) and emission-at-gold-tag
__device__ float g_expEm[B * S * T];    // 3 MB
__device__ float g_emAtTag[B * S];      // 64 KB

#define FMA2(acc, a, b) \
    asm("fma.rn.f32x2 %0, %1, %2, %0;" : "+l"(acc) : "l"(a), "l"(b))
#define ADD2(out, a, b) \
    asm("add.rn.f32x2 %0, %1, %2;" : "=l"(out) : "l"(a), "l"(b))
#define PACK2(out, lo, hi) \
    asm("mov.b64 %0, {%1, %2};" : "=l"(out) : "f"(lo), "f"(hi))
#define UNPACK2(lo, hi, in) \
    asm("mov.b64 {%0, %1}, %2;" : "=f"(lo), "=f"(hi) : "l"(in))

// ---------------------------------------------------------------------------
// Kernel A: emission = feat @ W + bias; store exp(emission) and em[b,s,tags[b,s]]
// Grid: 128 blocks x 256 threads. Each block: 128 rows x 48 cols, K=256.
// ---------------------------------------------------------------------------
__global__ __launch_bounds__(256) void emis_kernel(
    const float* __restrict__ feat,   // [B*S, H]
    const float* __restrict__ Wm,     // [H, T]
    const float* __restrict__ bias,   // [T]
    const int*   __restrict__ tags)   // [B*S]
{
    const int P = 129;                       // smem pitch (conflict break)
    __shared__ float sh_W[64 * T];           // 12 KB
    __shared__ float sh_feat[64 * P];        // 33 KB  (transposed: [k][row])

    const int tid  = threadIdx.x;
    const int row0 = blockIdx.x * 128;
    const int rg   = tid >> 3;   // 0..31 -> rows rg*4..rg*4+3
    const int cg   = tid & 7;    // 0..7  -> cols cg*6..cg*6+5

    float acc[4][6];
#pragma unroll
    for (int r = 0; r < 4; r++)
#pragma unroll
        for (int c = 0; c < 6; c++) acc[r][c] = 0.0f;

    for (int kc = 0; kc < H; kc += 64) {
        for (int u = tid; u < 64 * T; u += 256) sh_W[u] = Wm[kc * T + u];

#pragma unroll
        for (int m = 0; m < 8; m++) {
            int u   = tid + m * 256;      // 0..2047
            int row = u >> 4;             // 0..127
            int k4  = u & 15;             // 0..15 (float4 index)
            float4 v = reinterpret_cast<const float4*>(feat)
                        [(size_t)(row0 + row) * (H / 4) + (kc >> 2) + k4];
            sh_feat[(k4 * 4 + 0) * P + row] = v.x;
            sh_feat[(k4 * 4 + 1) * P + row] = v.y;
            sh_feat[(k4 * 4 + 2) * P + row] = v.z;
            sh_feat[(k4 * 4 + 3) * P + row] = v.w;
        }
        __syncthreads();

#pragma unroll 16
        for (int k = 0; k < 64; k++) {
            float f0 = sh_feat[k * P + rg * 4 + 0];
            float f1 = sh_feat[k * P + rg * 4 + 1];
            float f2 = sh_feat[k * P + rg * 4 + 2];
            float f3 = sh_feat[k * P + rg * 4 + 3];
            float2 w01 = *reinterpret_cast<const float2*>(&sh_W[k * T + cg * 6 + 0]);
            float2 w23 = *reinterpret_cast<const float2*>(&sh_W[k * T + cg * 6 + 2]);
            float2 w45 = *reinterpret_cast<const float2*>(&sh_W[k * T + cg * 6 + 4]);
            float w[6] = {w01.x, w01.y, w23.x, w23.y, w45.x, w45.y};
            float f[4] = {f0, f1, f2, f3};
#pragma unroll
            for (int r = 0; r < 4; r++)
#pragma unroll
                for (int c = 0; c < 6; c++)
                    acc[r][c] = fmaf(f[r], w[c], acc[r][c]);
        }
        __syncthreads();
    }

#pragma unroll
    for (int rr = 0; rr < 4; rr++) {
        int row = row0 + rg * 4 + rr;
        int tag = __ldg(&tags[row]);
#pragma unroll
        for (int cc = 0; cc < 6; cc++) {
            int c = cg * 6 + cc;
            float em = acc[rr][cc] + __ldg(&bias[c]);
            g_expEm[(size_t)row * T + c] = expf(em);
            if (c == tag) g_emAtTag[row] = em;
        }
    }
}

// ---------------------------------------------------------------------------
// Kernel B: single-warp forward recursion (warp-synchronous, no block barrier).
// Grid: B blocks x 32 threads. Lane l owns tags j0=l and j1=l+32 (j1<48 only
// for l<16; padded slots stay exactly 0). a[j] = exp(alpha[j] - K*ln2).
// Step: a'[j] = expEm[j] * dot(a, expT[:,j]).
//  - 12 LDS.128 shared by both dots, 48 fma.rn.f32x2
//  - __syncwarp only (no __syncthreads)
//  - power-of-2 rescale every 4 steps via one intra-warp redux.sync.max.u32
//  - expEm prefetch ring depth 4, guaranteed register-resident (macro unroll)
// ---------------------------------------------------------------------------

// One recursion step. PH = compile-time phase (0..3), MEASURE at PH==3.
#define STEP(sv, PH, MEASURE) do {                                            \
    const ulonglong2* av = reinterpret_cast<const ulonglong2*>(a_sh[buf]);    \
    unsigned long long A0=0ull,A1=0ull,A2=0ull,A3=0ull;                       \
    unsigned long long B0=0ull,B1=0ull,B2=0ull,B3=0ull;                       \
    _Pragma("unroll")                                                         \
    for (int q = 0; q < 12; q += 2) {                                         \
        ulonglong2 u = av[q];                                                 \
        ulonglong2 v = av[q + 1];                                             \
        FMA2(A0, u.x, eT2a[2*q+0]); FMA2(A1, u.y, eT2a[2*q+1]);               \
        FMA2(A2, v.x, eT2a[2*q+2]); FMA2(A3, v.y, eT2a[2*q+3]);               \
        FMA2(B0, u.x, eT2b[2*q+0]); FMA2(B1, u.y, eT2b[2*q+1]);               \
        FMA2(B2, v.x, eT2b[2*q+2]); FMA2(B3, v.y, eT2b[2*q+3]);               \
    }                                                                         \
    unsigned long long tA, tA2, tB, tB2;                                      \
    ADD2(tA, A0, A1); ADD2(tA2, A2, A3); ADD2(tA, tA, tA2);                   \
    ADD2(tB, B0, B1); ADD2(tB2, B2, B3); ADD2(tB, tB, tB2);                   \
    float d0l, d0h, d1l, d1h;                                                 \
    UNPACK2(d0l, d0h, tA); UNPACK2(d1l, d1h, tB);                             \
    float val0 = E0[PH] * (d0l + d0h) * invM;                                 \
    float val1 = E1[PH] * (d1l + d1h) * invM;                                 \
    invM = 1.0f;                                                              \
    {                                                                         \
        int sp = (sv) + 4;                                                    \
        E0[PH] = (sp < len) ? pe0[(size_t)sp * T] : 0.0f;                     \
        E1[PH] = (act1 && sp < len) ? pe1[(size_t)sp * T] : 0.0f;             \
    }                                                                         \
    const int nb = buf ^ 1;                                                   \
    a_sh[nb][l]      = val0;                                                  \
    a_sh[nb][l + 32] = val1;                                                  \
    if (MEASURE) {                                                            \
        uint32_t vb = __float_as_uint(fmaxf(val0, val1));                     \
        uint32_t wmax;                                                        \
        asm volatile("redux.sync.max.u32 %0, %1, 0xffffffff;"                 \
                     : "=r"(wmax) : "r"(vb));                                 \
        int k = (int)(wmax >> 23) - 127;      /* M in [2^k, 2^(k+1)) */       \
        invM  = __uint_as_float((uint32_t)(127 - k) << 23);  /* exact 2^-k */ \
        K    += k;                                                            \
        klast = k;                                                            \
    }                                                                         \
    __syncwarp();                                                             \
    buf = nb;                                                                 \
} while (0)

__global__ __launch_bounds__(32) void fwd_kernel(
    const float* __restrict__ trans,     // [T,T]
    const int*   __restrict__ lengths,   // [B]
    const int*   __restrict__ tags,      // [B,S]
    float*       __restrict__ out)       // [B]
{
    __shared__ float sh_trans[T * T];
    __shared__ __align__(16) float a_sh[2][64];

    const int l  = threadIdx.x;          // lane 0..31
    const int b  = blockIdx.x;
    const int j0 = l;                    // always < 48
    const int j1 = l + 32;               // valid tag only if < 48 (l < 16)
    const bool act1 = (j1 < T);

    for (int u = l; u < T * T; u += 32) sh_trans[u] = trans[u];
    __syncwarp();

    // transition columns j0 and j1 in registers, packed along 'from' pairs
    unsigned long long eT2a[T / 2], eT2b[T / 2];
    float eStop0, eStop1 = 0.0f;
#pragma unroll
    for (int i = 0; i < T / 2; i++) {
        float lo = expf(sh_trans[(2 * i + 0) * T + j0]);
        float hi = expf(sh_trans[(2 * i + 1) * T + j0]);
        PACK2(eT2a[i], lo, hi);
    }
    eStop0 = expf(sh_trans[j0 * T + STOP_IDX]);
    if (act1) {
#pragma unroll
        for (int i = 0; i < T / 2; i++) {
            float lo = expf(sh_trans[(2 * i + 0) * T + j1]);
            float hi = expf(sh_trans[(2 * i + 1) * T + j1]);
            PACK2(eT2b[i], lo, hi);
        }
        eStop1 = expf(sh_trans[j1 * T + STOP_IDX]);
    } else {
#pragma unroll
        for (int i = 0; i < T / 2; i++) eT2b[i] = 0ull;
    }

    // FIX (R7 bug): START_IDX=46 lives in the UPPER slot (lane 14, j1=46).
    a_sh[0][l]      = (j0 == START_IDX) ? 1.0f : 0.0f;
    a_sh[0][l + 32] = (j1 == START_IDX) ? 1.0f : 0.0f;
    __syncwarp();

    const int len = lengths[b];
    const float* pe0 = g_expEm + (size_t)b * S * T + j0;
    const float* pe1 = g_expEm + (size_t)b * S * T + j1;

    // expEm prefetch ring, depth 4 (register-resident: all indices constant)
    float E0[4], E1[4];
#pragma unroll
    for (int q = 0; q < 4; q++) {
        E0[q] = (q < len) ? pe0[(size_t)q * T] : 0.0f;
        E1[q] = (act1 && q < len) ? pe1[(size_t)q * T] : 0.0f;
    }

    int   K     = 0;      // total shifted-out exponent (exact)
    int   klast = 0;      // k of most recent measure (tail fixup)
    int   buf   = 0;
    float invM  = 1.0f;   // pending 2^-k to apply on next step

    int s = 0;
    for (; s + 4 <= len; s += 4) {
        STEP(s + 0, 0, false);
        STEP(s + 1, 1, false);
        STEP(s + 2, 2, false);
        STEP(s + 3, 3, true);
    }
    if (s + 0 < len) STEP(s + 0, 0, false);
    if (s + 1 < len) STEP(s + 1, 1, false);
    if (s + 2 < len) STEP(s + 2, 2, false);

    // if the sequence ended on a measure step, its rescale was never applied
    if ((len & 3) == 0) K -= klast;

    // terminal: logZ = K*ln2 + log( sum_j a[j] * exp(trans[j][STOP]) )
    float tj = a_sh[buf][l] * eStop0 + a_sh[buf][l + 32] * eStop1;
#pragma unroll
    for (int o = 16; o; o >>= 1) tj += __shfl_xor_sync(0xffffffffu, tj, o);
    const float logZ = (float)K * 0.6931471805599453f + logf(tj);

    // gold score
    const int* btags = tags + b * S;
    float g = 0.0f;
    for (int t = l; t < len; t += 32) {
        int to   = btags[t];
        int from = (t == 0) ? START_IDX : btags[t - 1];
        g += sh_trans[from * T + to] + g_emAtTag[(size_t)b * S + t];
    }
#pragma unroll
    for (int o = 16; o; o >>= 1) g += __shfl_xor_sync(0xffffffffu, g, o);

    if (l == 0) {
        float gold = g + sh_trans[btags[len - 1] * T + STOP_IDX];
        out[b] = logZ - gold;
    }
}

// ---------------------------------------------------------------------------
extern "C" void kernel_launch(void* const* d_in, const int* in_sizes, int n_in,
                              void* d_out, int out_size)
{
    const float* feat    = (const float*)d_in[0];  // lstm_features [B,S,H]
    const float* Wm      = (const float*)d_in[1];  // emission_w [H,T]
    const float* bias    = (const float*)d_in[2];  // emission_b [T]
    const float* trans   = (const float*)d_in[3];  // transitions [T,T]
    const int*   lengths = (const int*)d_in[4];    // [B]
    const int*   tags    = (const int*)d_in[5];    // [B,S]
    float*       out     = (float*)d_out;          // [B]

    emis_kernel<<<(B * S) / 128, 256>>>(feat, Wm, bias, tags);
    fwd_kernel<<<B, 32>>>(trans, lengths, tags, out);
}